// round 5
// baseline (speedup 1.0000x reference)
#include <cuda_runtime.h>

// ModifiedLogicSegLoss: loss = sum_{b,c} w[c] * (softplus(x) - t*x)
//   w[c] = sum_l La[l,c]*lam[l] / 128   (levels partition classes; clamp never fires)
// B=262144, C=128 -> 2^23 float4 vectors per input array.
// Mainloop is software-pipelined: depth-2 prefetch (4 float4 always in flight
// per thread) so load issue never stalls behind the MUFU chain.

#define NBLOCKS   1024
#define NTHREADS  256
#define NC        128
#define NVEC      (1u << 23)                       // 8,388,608 float4 elements
#define STRIDE    (NBLOCKS * NTHREADS)             // 262144, multiple of 32
#define ITERS     (NVEC / STRIDE)                  // 32, compile-time

__device__ float g_partials[NBLOCKS];
__device__ unsigned int g_done = 0;                // re-armed by last block

__device__ __forceinline__ unsigned ticket_acq_rel(unsigned int* p) {
    unsigned old;
    asm volatile("atom.global.add.acq_rel.gpu.u32 %0, [%1], 1;"
                 : "=r"(old) : "l"(p) : "memory");
    return old;
}

__device__ __forceinline__ float bce_elem(float x, float t) {
    // softplus(x) - t*x, stable form: max(x,0) + log1p(exp(-|x|))
    float e  = __expf(-fabsf(x));
    float sp = fmaxf(x, 0.0f) + __logf(1.0f + e);
    return fmaf(-t, x, sp);
}

__device__ __forceinline__ float quad(const float4 x, const float4 t,
                                      const float4 wv, float acc) {
    float s =      wv.x * bce_elem(x.x, t.x);
    s = fmaf(wv.y, bce_elem(x.y, t.y), s);
    s = fmaf(wv.z, bce_elem(x.z, t.z), s);
    s = fmaf(wv.w, bce_elem(x.w, t.w), s);
    return acc + s;
}

__global__ void __launch_bounds__(NTHREADS, 5)
loss_fused(const float4* __restrict__ yp, const float4* __restrict__ yt,
           const float*  __restrict__ La, const float*  __restrict__ lam,
           float* __restrict__ out) {
    __shared__ __align__(16) float w[NC];
    __shared__ float wred[NTHREADS / 32];
    __shared__ bool s_last;
    const int tid = threadIdx.x;

    // Build per-class weights once per block (La: [4,128], lam: [4])
    if (tid < NC) {
        float a = 0.0f;
        #pragma unroll
        for (int l = 0; l < 4; ++l)
            a = fmaf(La[l * NC + tid], lam[l], a);
        w[tid] = a * (1.0f / (float)NC);
    }
    __syncthreads();

    const unsigned gid = blockIdx.x * NTHREADS + tid;
    // Stride is a multiple of 32 -> class-quad index is loop-invariant.
    const float4 wv = reinterpret_cast<const float4*>(w)[gid & 31];

    // Prime the pipeline: 2 vector-pairs (4 float4) in flight.
    float4 x0 = __ldcs(yp + gid);
    float4 t0 = __ldcs(yt + gid);
    float4 x1 = __ldcs(yp + gid + STRIDE);
    float4 t1 = __ldcs(yt + gid + STRIDE);

    float acc0 = 0.0f, acc1 = 0.0f;
    unsigned v = gid;
    #pragma unroll
    for (int i = 0; i < ITERS - 2; i += 2) {
        const unsigned vn = v + 2u * STRIDE;
        // Prefetch the next pair BEFORE touching the current one.
        const float4 nx0 = __ldcs(yp + vn);
        const float4 nt0 = __ldcs(yt + vn);
        const float4 nx1 = __ldcs(yp + vn + STRIDE);
        const float4 nt1 = __ldcs(yt + vn + STRIDE);
        acc0 = quad(x0, t0, wv, acc0);
        acc1 = quad(x1, t1, wv, acc1);
        x0 = nx0; t0 = nt0; x1 = nx1; t1 = nt1;
        v = vn;
    }
    acc0 = quad(x0, t0, wv, acc0);
    acc1 = quad(x1, t1, wv, acc1);
    float acc = acc0 + acc1;

    // Intra-block reduce: warp shfl, then warp 0 folds the 8 warp sums.
    #pragma unroll
    for (int o = 16; o > 0; o >>= 1)
        acc += __shfl_xor_sync(0xffffffffu, acc, o);
    if ((tid & 31) == 0) wred[tid >> 5] = acc;
    __syncthreads();

    if (tid < 32) {
        float a = (tid < NTHREADS / 32) ? wred[tid] : 0.0f;
        #pragma unroll
        for (int o = 4; o > 0; o >>= 1)
            a += __shfl_xor_sync(0xffffffffu, a, o);
        if (tid == 0) {
            g_partials[blockIdx.x] = a;
            // acq_rel ticket: release orders the partial store before the
            // increment; the winner's acquire covers its subsequent reads.
            unsigned old = ticket_acq_rel(&g_done);
            s_last = (old == NBLOCKS - 1);
        }
    }
    __syncthreads();

    // Last-arriving block performs the fixed-order final reduction.
    if (s_last) {
        __shared__ float fin[NTHREADS / 32];
        // 1024 partials = 256 float4: one per thread, fixed order, L1-bypass.
        const float4 p = __ldcg(reinterpret_cast<const float4*>(g_partials) + tid);
        float a = ((p.x + p.y) + (p.z + p.w));
        #pragma unroll
        for (int o = 16; o > 0; o >>= 1)
            a += __shfl_xor_sync(0xffffffffu, a, o);
        if ((tid & 31) == 0) fin[tid >> 5] = a;
        if (tid == 0) g_done = 0u;                 // re-arm for next replay
        __syncthreads();

        if (tid < 32) {
            float b = (tid < NTHREADS / 32) ? fin[tid] : 0.0f;
            #pragma unroll
            for (int o = 4; o > 0; o >>= 1)
                b += __shfl_xor_sync(0xffffffffu, b, o);
            if (tid == 0) out[0] = b;
        }
    }
}

extern "C" void kernel_launch(void* const* d_in, const int* in_sizes, int n_in,
                              void* d_out, int out_size) {
    (void)in_sizes; (void)n_in; (void)out_size;
    loss_fused<<<NBLOCKS, NTHREADS>>>(
        (const float4*)d_in[0], (const float4*)d_in[1],
        (const float*)d_in[2],  (const float*)d_in[3],
        (float*)d_out);
}

// round 6
// speedup vs baseline: 1.0832x; 1.0832x over previous
#include <cuda_runtime.h>

// ModifiedLogicSegLoss: loss = sum_{b,c} w[c] * (softplus(x) - t*x)
//   w[c] = sum_l La[l,c]*lam[l] / 128   (levels partition classes; clamp never fires)
// B=262144, C=128 -> 2^23 float4 vectors per input array.
// Grid = 148 SMs x 8 CTAs (regs=32 -> exactly 8 CTAs/SM fit): one perfectly
// balanced wave, eliminating the 6-vs-7-CTAs/SM tail of a 1024-block grid.

#define NSM       148
#define NBLOCKS   (NSM * 8)                        // 1184, one exact wave
#define NTHREADS  256
#define NC        128
#define NVEC      (1u << 23)                       // 8,388,608 float4 elements
#define STRIDE    (NBLOCKS * NTHREADS)             // 303104, multiple of 32

__device__ float g_partials[NBLOCKS];
__device__ unsigned int g_done = 0;                // re-armed by last block

__device__ __forceinline__ unsigned ticket_acq_rel(unsigned int* p) {
    unsigned old;
    asm volatile("atom.global.add.acq_rel.gpu.u32 %0, [%1], 1;"
                 : "=r"(old) : "l"(p) : "memory");
    return old;
}

__device__ __forceinline__ float bce_elem(float x, float t) {
    // softplus(x) - t*x, stable form: max(x,0) + log1p(exp(-|x|))
    float e  = __expf(-fabsf(x));
    float sp = fmaxf(x, 0.0f) + __logf(1.0f + e);
    return fmaf(-t, x, sp);
}

__global__ void __launch_bounds__(NTHREADS)
loss_fused(const float4* __restrict__ yp, const float4* __restrict__ yt,
           const float*  __restrict__ La, const float*  __restrict__ lam,
           float* __restrict__ out) {
    __shared__ __align__(16) float w[NC];
    __shared__ float wred[NTHREADS / 32];
    __shared__ bool s_last;
    const int tid = threadIdx.x;

    // Build per-class weights once per block (La: [4,128], lam: [4])
    if (tid < NC) {
        float a = 0.0f;
        #pragma unroll
        for (int l = 0; l < 4; ++l)
            a = fmaf(La[l * NC + tid], lam[l], a);
        w[tid] = a * (1.0f / (float)NC);
    }
    __syncthreads();

    const unsigned gid = blockIdx.x * NTHREADS + tid;
    // Stride is a multiple of 32 -> class-quad index is loop-invariant.
    const float4 wv = reinterpret_cast<const float4*>(w)[gid & 31];

    float acc = 0.0f;
    #pragma unroll 8
    for (unsigned v = gid; v < NVEC; v += STRIDE) {
        const float4 x = __ldcs(yp + v);           // streaming: evict-first
        const float4 t = __ldcs(yt + v);
        float s =      wv.x * bce_elem(x.x, t.x);
        s = fmaf(wv.y, bce_elem(x.y, t.y), s);
        s = fmaf(wv.z, bce_elem(x.z, t.z), s);
        s = fmaf(wv.w, bce_elem(x.w, t.w), s);
        acc += s;
    }

    // Intra-block reduce: warp shfl, then warp 0 folds the 8 warp sums.
    #pragma unroll
    for (int o = 16; o > 0; o >>= 1)
        acc += __shfl_xor_sync(0xffffffffu, acc, o);
    if ((tid & 31) == 0) wred[tid >> 5] = acc;
    __syncthreads();

    if (tid < 32) {
        float a = (tid < NTHREADS / 32) ? wred[tid] : 0.0f;
        #pragma unroll
        for (int o = 4; o > 0; o >>= 1)
            a += __shfl_xor_sync(0xffffffffu, a, o);
        if (tid == 0) {
            g_partials[blockIdx.x] = a;
            // acq_rel ticket: release orders the partial store before the
            // increment; the winner's acquire covers its subsequent reads.
            unsigned old = ticket_acq_rel(&g_done);
            s_last = (old == NBLOCKS - 1);
        }
    }
    __syncthreads();

    // Last-arriving block performs the fixed-order final reduction.
    if (s_last) {
        __shared__ float fin[NTHREADS / 32];
        // 1184 partials = 296 float4: 256 threads read 1-2 each, fixed order,
        // L1-bypass (__ldcg) to see other SMs' published values.
        const float4* gp4 = reinterpret_cast<const float4*>(g_partials);
        float4 p = __ldcg(gp4 + tid);
        float a = ((p.x + p.y) + (p.z + p.w));
        if (tid < NBLOCKS / 4 - NTHREADS) {        // remaining 40 float4
            p = __ldcg(gp4 + NTHREADS + tid);
            a += ((p.x + p.y) + (p.z + p.w));
        }
        #pragma unroll
        for (int o = 16; o > 0; o >>= 1)
            a += __shfl_xor_sync(0xffffffffu, a, o);
        if ((tid & 31) == 0) fin[tid >> 5] = a;
        if (tid == 0) g_done = 0u;                 // re-arm for next replay
        __syncthreads();

        if (tid < 32) {
            float b = (tid < NTHREADS / 32) ? fin[tid] : 0.0f;
            #pragma unroll
            for (int o = 4; o > 0; o >>= 1)
                b += __shfl_xor_sync(0xffffffffu, b, o);
            if (tid == 0) out[0] = b;
        }
    }
}

extern "C" void kernel_launch(void* const* d_in, const int* in_sizes, int n_in,
                              void* d_out, int out_size) {
    (void)in_sizes; (void)n_in; (void)out_size;
    loss_fused<<<NBLOCKS, NTHREADS>>>(
        (const float4*)d_in[0], (const float4*)d_in[1],
        (const float*)d_in[2],  (const float*)d_in[3],
        (float*)d_out);
}

// round 8
// speedup vs baseline: 1.1547x; 1.0660x over previous
#include <cuda_runtime.h>
#include <cstdint>

// ModifiedLogicSegLoss: loss = sum_{b,c} w[c] * (softplus(x) - t*x)
//   w[c] = sum_l La[l,c]*lam[l] / 128   (levels partition classes; clamp never fires)
// B=262144, C=128 -> 2^23 float4 vectors per input array.
// cp.async (LDGSTS) pipeline with PRIVATE per-thread smem slots: loads carry
// no destination register, so load issue is fully decoupled from the MUFU
// compute chain; no __syncthreads in the pipeline (each thread reads only the
// slot it filled). 3 stages, 8 CTAs/SM, regs capped at 32.

#define NBLOCKS   1024
#define NTHREADS  256
#define NC        128
#define NVEC      (1u << 23)                       // 8,388,608 float4 elements
#define STRIDE    (NBLOCKS * NTHREADS)             // 262144, multiple of 32
#define ITERS     (NVEC / STRIDE)                  // 32, compile-time
#define STAGES    3
#define STAGE_B   (NTHREADS * 16)                  // 4096 bytes per stage row

__device__ float g_partials[NBLOCKS];
__device__ unsigned int g_done = 0;                // re-armed by last block

__device__ __forceinline__ unsigned ticket_acq_rel(unsigned int* p) {
    unsigned old;
    asm volatile("atom.global.add.acq_rel.gpu.u32 %0, [%1], 1;"
                 : "=r"(old) : "l"(p) : "memory");
    return old;
}

__device__ __forceinline__ unsigned int smem_u32(const void* p) {
    return (unsigned int)__cvta_generic_to_shared(p);
}

#define CP16(saddr, gptr) \
    asm volatile("cp.async.cg.shared.global [%0], [%1], 16;" \
                 :: "r"(saddr), "l"(gptr) : "memory")
#define CPCOMMIT() asm volatile("cp.async.commit_group;" ::: "memory")
#define CPWAIT(n)  asm volatile("cp.async.wait_group %0;" :: "n"(n) : "memory")

__device__ __forceinline__ float bce_elem(float x, float t) {
    // softplus(x) - t*x, stable form: max(x,0) + log1p(exp(-|x|))
    float e  = __expf(-fabsf(x));
    float sp = fmaxf(x, 0.0f) + __logf(1.0f + e);
    return fmaf(-t, x, sp);
}

__global__ void __launch_bounds__(NTHREADS, 8)
loss_fused(const float4* __restrict__ yp, const float4* __restrict__ yt,
           const float*  __restrict__ La, const float*  __restrict__ lam,
           float* __restrict__ out) {
    __shared__ __align__(16) float4 sx[STAGES][NTHREADS];   // yp slots
    __shared__ __align__(16) float4 st4[STAGES][NTHREADS];  // yt slots
    __shared__ __align__(16) float w[NC];
    __shared__ float wred[NTHREADS / 32];
    __shared__ bool s_last;
    const int tid = threadIdx.x;

    // Build per-class weights once per block (La: [4,128], lam: [4])
    if (tid < NC) {
        float a = 0.0f;
        #pragma unroll
        for (int l = 0; l < 4; ++l)
            a = fmaf(La[l * NC + tid], lam[l], a);
        w[tid] = a * (1.0f / (float)NC);
    }
    __syncthreads();

    const unsigned gid = blockIdx.x * NTHREADS + tid;
    // Stride is a multiple of 32 -> class-quad index is loop-invariant.
    const float4 wv = reinterpret_cast<const float4*>(w)[gid & 31];

    const unsigned int ax = smem_u32(&sx[0][tid]);
    const unsigned int at = smem_u32(&st4[0][tid]);

    // Prologue: fill STAGES stages (one commit group per stage).
    #pragma unroll
    for (int s = 0; s < STAGES; ++s) {
        const unsigned v = gid + (unsigned)s * STRIDE;
        CP16(ax + s * STAGE_B, yp + v);
        CP16(at + s * STAGE_B, yt + v);
        CPCOMMIT();
    }

    float acc = 0.0f;
    #pragma unroll
    for (int i = 0; i < ITERS; ++i) {
        CPWAIT(STAGES - 1);                    // oldest stage (i) has landed
        const int s = i % STAGES;
        const float4 x = sx[s][tid];           // private slot: no barrier
        const float4 t = st4[s][tid];
        asm volatile("" ::: "memory");         // reads precede the refill
        if (i + STAGES < ITERS) {
            const unsigned vn = gid + (unsigned)(i + STAGES) * STRIDE;
            CP16(ax + s * STAGE_B, yp + vn);
            CP16(at + s * STAGE_B, yt + vn);
            CPCOMMIT();
        }
        float sum =      wv.x * bce_elem(x.x, t.x);
        sum = fmaf(wv.y, bce_elem(x.y, t.y), sum);
        sum = fmaf(wv.z, bce_elem(x.z, t.z), sum);
        sum = fmaf(wv.w, bce_elem(x.w, t.w), sum);
        acc += sum;
    }

    // Intra-block reduce: warp shfl, then warp 0 folds the 8 warp sums.
    #pragma unroll
    for (int o = 16; o > 0; o >>= 1)
        acc += __shfl_xor_sync(0xffffffffu, acc, o);
    if ((tid & 31) == 0) wred[tid >> 5] = acc;
    __syncthreads();

    if (tid < 32) {
        float a = (tid < NTHREADS / 32) ? wred[tid] : 0.0f;
        #pragma unroll
        for (int o = 4; o > 0; o >>= 1)
            a += __shfl_xor_sync(0xffffffffu, a, o);
        if (tid == 0) {
            g_partials[blockIdx.x] = a;
            // acq_rel ticket: release orders the partial store before the
            // increment; the winner's acquire covers its subsequent reads.
            unsigned old = ticket_acq_rel(&g_done);
            s_last = (old == NBLOCKS - 1);
        }
    }
    __syncthreads();

    // Last-arriving block performs the fixed-order final reduction.
    if (s_last) {
        __shared__ float fin[NTHREADS / 32];
        // 1024 partials = 256 float4: one per thread, fixed order, L1-bypass.
        const float4 p = __ldcg(reinterpret_cast<const float4*>(g_partials) + tid);
        float a = ((p.x + p.y) + (p.z + p.w));
        #pragma unroll
        for (int o = 16; o > 0; o >>= 1)
            a += __shfl_xor_sync(0xffffffffu, a, o);
        if ((tid & 31) == 0) fin[tid >> 5] = a;
        if (tid == 0) g_done = 0u;                 // re-arm for next replay
        __syncthreads();

        if (tid < 32) {
            float b = (tid < NTHREADS / 32) ? fin[tid] : 0.0f;
            #pragma unroll
            for (int o = 4; o > 0; o >>= 1)
                b += __shfl_xor_sync(0xffffffffu, b, o);
            if (tid == 0) out[0] = b;
        }
    }
}

extern "C" void kernel_launch(void* const* d_in, const int* in_sizes, int n_in,
                              void* d_out, int out_size) {
    (void)in_sizes; (void)n_in; (void)out_size;
    loss_fused<<<NBLOCKS, NTHREADS>>>(
        (const float4*)d_in[0], (const float4*)d_in[1],
        (const float*)d_in[2],  (const float*)d_in[3],
        (float*)d_out);
}

// round 9
// speedup vs baseline: 1.1733x; 1.0161x over previous
#include <cuda_runtime.h>

// ModifiedLogicSegLoss: loss = sum_{b,c} w[c] * (softplus(x) - t*x)
//   w[c] = sum_l La[l,c]*lam[l] / 128   (levels partition classes; clamp never fires)
// B=262144, C=128 -> 2^23 float4 vectors per input array.
// R4 mainloop (plain LDG.128 + unrolled MUFU chain, regs<=32, 8 CTAs/SM),
// with the 32-iteration loop FULLY unrolled: removes all loop-control ALU
// and lets ptxas schedule loads across iteration boundaries.

#define NBLOCKS   1024
#define NTHREADS  256
#define NC        128
#define NVEC      (1u << 23)                       // 8,388,608 float4 elements
#define STRIDE    (NBLOCKS * NTHREADS)             // 262144, multiple of 32
#define ITERS     (NVEC / STRIDE)                  // 32, compile-time

__device__ float g_partials[NBLOCKS];
__device__ unsigned int g_done = 0;                // re-armed by last block

__device__ __forceinline__ unsigned ticket_acq_rel(unsigned int* p) {
    unsigned old;
    asm volatile("atom.global.add.acq_rel.gpu.u32 %0, [%1], 1;"
                 : "=r"(old) : "l"(p) : "memory");
    return old;
}

__device__ __forceinline__ float bce_elem(float x, float t) {
    // softplus(x) - t*x, stable form: max(x,0) + log1p(exp(-|x|))
    float e  = __expf(-fabsf(x));
    float sp = fmaxf(x, 0.0f) + __logf(1.0f + e);
    return fmaf(-t, x, sp);
}

__global__ void __launch_bounds__(NTHREADS, 8)
loss_fused(const float4* __restrict__ yp, const float4* __restrict__ yt,
           const float*  __restrict__ La, const float*  __restrict__ lam,
           float* __restrict__ out) {
    __shared__ __align__(16) float w[NC];
    __shared__ float wred[NTHREADS / 32];
    __shared__ bool s_last;
    const int tid = threadIdx.x;

    // Build per-class weights once per block (La: [4,128], lam: [4])
    if (tid < NC) {
        float a = 0.0f;
        #pragma unroll
        for (int l = 0; l < 4; ++l)
            a = fmaf(La[l * NC + tid], lam[l], a);
        w[tid] = a * (1.0f / (float)NC);
    }
    __syncthreads();

    const unsigned gid = blockIdx.x * NTHREADS + tid;
    // Stride is a multiple of 32 -> class-quad index is loop-invariant.
    const float4 wv = reinterpret_cast<const float4*>(w)[gid & 31];

    float acc = 0.0f;
    #pragma unroll
    for (int i = 0; i < ITERS; ++i) {              // fully unrolled (32x)
        const unsigned v = gid + (unsigned)i * STRIDE;
        const float4 x = __ldcs(yp + v);           // streaming: evict-first
        const float4 t = __ldcs(yt + v);
        float s =      wv.x * bce_elem(x.x, t.x);
        s = fmaf(wv.y, bce_elem(x.y, t.y), s);
        s = fmaf(wv.z, bce_elem(x.z, t.z), s);
        s = fmaf(wv.w, bce_elem(x.w, t.w), s);
        acc += s;
    }

    // Intra-block reduce: warp shfl, then warp 0 folds the 8 warp sums.
    #pragma unroll
    for (int o = 16; o > 0; o >>= 1)
        acc += __shfl_xor_sync(0xffffffffu, acc, o);
    if ((tid & 31) == 0) wred[tid >> 5] = acc;
    __syncthreads();

    if (tid < 32) {
        float a = (tid < NTHREADS / 32) ? wred[tid] : 0.0f;
        #pragma unroll
        for (int o = 4; o > 0; o >>= 1)
            a += __shfl_xor_sync(0xffffffffu, a, o);
        if (tid == 0) {
            g_partials[blockIdx.x] = a;
            // acq_rel ticket: release orders the partial store before the
            // increment; the winner's acquire covers its subsequent reads.
            unsigned old = ticket_acq_rel(&g_done);
            s_last = (old == NBLOCKS - 1);
        }
    }
    __syncthreads();

    // Last-arriving block performs the fixed-order final reduction.
    if (s_last) {
        __shared__ float fin[NTHREADS / 32];
        // 1024 partials = 256 float4: one per thread, fixed order, L1-bypass.
        const float4 p = __ldcg(reinterpret_cast<const float4*>(g_partials) + tid);
        float a = ((p.x + p.y) + (p.z + p.w));
        #pragma unroll
        for (int o = 16; o > 0; o >>= 1)
            a += __shfl_xor_sync(0xffffffffu, a, o);
        if ((tid & 31) == 0) fin[tid >> 5] = a;
        if (tid == 0) g_done = 0u;                 // re-arm for next replay
        __syncthreads();

        if (tid < 32) {
            float b = (tid < NTHREADS / 32) ? fin[tid] : 0.0f;
            #pragma unroll
            for (int o = 4; o > 0; o >>= 1)
                b += __shfl_xor_sync(0xffffffffu, b, o);
            if (tid == 0) out[0] = b;
        }
    }
}

extern "C" void kernel_launch(void* const* d_in, const int* in_sizes, int n_in,
                              void* d_out, int out_size) {
    (void)in_sizes; (void)n_in; (void)out_size;
    loss_fused<<<NBLOCKS, NTHREADS>>>(
        (const float4*)d_in[0], (const float4*)d_in[1],
        (const float*)d_in[2],  (const float*)d_in[3],
        (float*)d_out);
}